// round 7
// baseline (speedup 1.0000x reference)
#include <cuda_runtime.h>
#include <math.h>

#define B 8
#define N 1024
#define C 256
#define K 256
#define C2 512
#define SCALE 0.17677669529663687f   // (C/H)^-0.5 = 1/sqrt(32)

// Output layout: [new_X (8*256*256) | new_adj (8*256*256) | new_mask (8*256)]
#define OUT_ADJ_OFF  (B*K*C)
#define OUT_MASK_OFF (2*B*K*C)

#define NCHUNK 64      // partial-sum chunks per batch (16 rows each)

// ---- scratch ----
__device__ float d_part[B*NCHUNK*C];
__device__ float d_u[B*C];
__device__ float d_scores[B*N];
__device__ unsigned long long d_runs[B*4*256];   // 4 sorted runs per batch
__device__ int   d_idxg[B*K];
__device__ float d_gate[B*K];
__device__ float d_nm[B*K];

// ---------------------------------------------------------------------------
// K1: partial column sums of X (verbatim R2 — proven rounding).
// ---------------------------------------------------------------------------
__global__ void k_partial(const float* __restrict__ X) {
    int b = blockIdx.y, ch = blockIdx.x, c = threadIdx.x;
    const float* xp = X + ((size_t)b * N + (size_t)ch * 16) * C + c;
    float s = 0.f;
    #pragma unroll
    for (int r = 0; r < 16; r++) s += xp[(size_t)r * C];
    d_part[(b * NCHUNK + ch) * C + c] = s;
}

// ---------------------------------------------------------------------------
// K2: Xsum finish + two matvecs (verbatim R2 — proven rounding).
// ---------------------------------------------------------------------------
__global__ void k_uvec(const float* __restrict__ Wqkv) {
    int b = blockIdx.x, t = threadIdx.x;
    __shared__ float xs[C];
    __shared__ float ks[C];
    float s = 0.f;
    #pragma unroll
    for (int ch = 0; ch < NCHUNK; ch++) s += d_part[(b * NCHUNK + ch) * C + t];
    xs[t] = s;
    __syncthreads();
    float ka = 0.f;
    for (int c = 0; c < C; c++) ka += xs[c] * Wqkv[(size_t)c * C2 + C + t];
    ks[t] = ka;
    __syncthreads();
    const float* wrow = Wqkv + (size_t)t * C2;
    float ua = 0.f;
    for (int j = 0; j < C; j++) ua += wrow[j] * ks[j];
    d_u[b * C + t] = ua;
}

// ---------------------------------------------------------------------------
// K3: scores (verbatim R2 — proven rounding).
// ---------------------------------------------------------------------------
__global__ void k_scores(const float* __restrict__ X,
                         const float* __restrict__ mask) {
    int b = blockIdx.y, t = threadIdx.x;
    __shared__ float us[C];
    us[t] = d_u[b * C + t];
    __syncthreads();
    int warp = t >> 5, lane = t & 31;
    int n = blockIdx.x * 8 + warp;
    const float4* xr = (const float4*)(X + ((size_t)b * N + n) * C);
    const float4* ur = (const float4*)us;
    float acc = 0.f;
    #pragma unroll
    for (int it = 0; it < 2; it++) {
        float4 xv = xr[lane + it * 32];
        float4 uv = ur[lane + it * 32];
        acc += xv.x * uv.x + xv.y * uv.y + xv.z * uv.z + xv.w * uv.w;
    }
    #pragma unroll
    for (int o = 16; o; o >>= 1) acc += __shfl_xor_sync(0xffffffffu, acc, o);
    if (lane == 0) {
        float m = mask[b * N + n];
        d_scores[b * N + n] = (m > 0.f) ? SCALE * acc : -1e9f;
    }
}

// ---------------------------------------------------------------------------
// K4a: sort each 256-element quarter ascending, fully in-warp.
// grid (4, 8), 32 threads, 8 elems/thread (e = 8t + r).
// Same key construction and stage mechanics as the R6-proven sort; with 256
// elements the max shuffle distance is 128/8 = 16, so no shared stages exist.
// Key = (~orderedFloat(score) << 32) | global_idx.
// ---------------------------------------------------------------------------
__global__ void __launch_bounds__(32, 8)
k_sort256() {
    int q = blockIdx.x, b = blockIdx.y, t = threadIdx.x;
    unsigned long long v[8];
    {
        const float* sc = d_scores + b * N + q * 256 + t * 8;
        #pragma unroll
        for (int r = 0; r < 8; r++) {
            float f = sc[r];
            unsigned u = __float_as_uint(f);
            u = (u & 0x80000000u) ? ~u : (u | 0x80000000u);
            v[r] = ((unsigned long long)(~u) << 32)
                 | (unsigned)(q * 256 + t * 8 + r);
        }
    }
    #pragma unroll
    for (unsigned k = 2; k <= 256; k <<= 1) {
        #pragma unroll
        for (unsigned j = 128; j > 0; j >>= 1) {
            if (j > (k >> 1)) continue;
            if (j >= 8) {
                unsigned jt = j >> 3;                  // lane distance 1..16
                bool lower = ((t & jt) == 0);
                bool up    = ((t & (k >> 3)) == 0);    // k>=16 here
                bool takeMin = (lower == up);
                #pragma unroll
                for (int r = 0; r < 8; r++) {
                    unsigned long long w = __shfl_xor_sync(0xffffffffu, v[r], jt);
                    v[r] = takeMin ? (v[r] < w ? v[r] : w)
                                   : (v[r] > w ? v[r] : w);
                }
            } else {
                #pragma unroll
                for (int r = 0; r < 8; r++) {
                    if ((r & j) == 0) {
                        int rp = r | j;
                        unsigned e = (unsigned)(t * 8 + r);
                        bool up = ((e & k) == 0);
                        unsigned long long a = v[r], bb = v[rp];
                        unsigned long long mn = a < bb ? a : bb;
                        unsigned long long mx = a < bb ? bb : a;
                        v[r]  = up ? mn : mx;
                        v[rp] = up ? mx : mn;
                    }
                }
            }
        }
    }
    unsigned long long* dst = d_runs + ((b * 4 + q) * 256) + t * 8;
    #pragma unroll
    for (int r = 0; r < 8; r++) dst[r] = v[r];
}

// ---------------------------------------------------------------------------
// K4b: bitonic top-k reduction of 4 ascending runs -> sorted top-256.
// grid (8), 32 threads, 8 elems/thread.
// min-merge: C[e] = min(P[e], Q[255-e]) = 256 smallest of P∪Q (bitonic),
// then 8 ascending merge stages re-sort. Applied twice pairwise + once final.
// Exact integer comparisons on the same keys => bit-identical to a full sort.
// ---------------------------------------------------------------------------
__device__ __forceinline__ void merge_sort256(unsigned long long* P,
                                              const unsigned long long* Q,
                                              int t) {
    // C[e] = min(P[e], Q[255-e]); 255-e = 8*(31-t) + (7-r)
    #pragma unroll
    for (int r = 0; r < 8; r++) {
        unsigned long long w = __shfl_xor_sync(0xffffffffu, Q[7 - r], 31);
        P[r] = P[r] < w ? P[r] : w;
    }
    // ascending bitonic merge of the bitonic 256-seq: j = 128..1, up always
    #pragma unroll
    for (unsigned j = 128; j >= 8; j >>= 1) {
        unsigned jt = j >> 3;
        bool takeMin = ((t & jt) == 0);
        #pragma unroll
        for (int r = 0; r < 8; r++) {
            unsigned long long w = __shfl_xor_sync(0xffffffffu, P[r], jt);
            P[r] = takeMin ? (P[r] < w ? P[r] : w)
                           : (P[r] > w ? P[r] : w);
        }
    }
    #pragma unroll
    for (unsigned j = 4; j > 0; j >>= 1) {
        #pragma unroll
        for (int r = 0; r < 8; r++) {
            if ((r & j) == 0) {
                int rp = r | j;
                unsigned long long a = P[r], bb = P[rp];
                P[r]  = a < bb ? a : bb;
                P[rp] = a < bb ? bb : a;
            }
        }
    }
}

__global__ void __launch_bounds__(32, 8)
k_merge(const float* __restrict__ mask, float* __restrict__ out) {
    int b = blockIdx.x, t = threadIdx.x;

    // mask sum -> k_i (0/1 values: exact in any order)
    float msum = 0.f;
    {
        const float4* mk = (const float4*)(mask + b * N);
        #pragma unroll
        for (int i = 0; i < 8; i++) {
            float4 m4 = mk[t + 32 * i];
            msum += m4.x + m4.y + m4.z + m4.w;
        }
        #pragma unroll
        for (int o = 16; o; o >>= 1) msum += __shfl_xor_sync(0xffffffffu, msum, o);
    }
    int ki = (int)ceilf(0.25f * msum);

    const unsigned long long* runs = d_runs + b * 4 * 256;
    unsigned long long A[8], Btmp[8];

    // level 1a: runs 0,1
    #pragma unroll
    for (int r = 0; r < 8; r++) A[r]    = runs[0 * 256 + t * 8 + r];
    #pragma unroll
    for (int r = 0; r < 8; r++) Btmp[r] = runs[1 * 256 + t * 8 + r];
    merge_sort256(A, Btmp, t);

    // level 1b: runs 2,3
    unsigned long long C2r[8];
    #pragma unroll
    for (int r = 0; r < 8; r++) C2r[r]  = runs[2 * 256 + t * 8 + r];
    #pragma unroll
    for (int r = 0; r < 8; r++) Btmp[r] = runs[3 * 256 + t * 8 + r];
    merge_sort256(C2r, Btmp, t);

    // level 2
    merge_sort256(A, C2r, t);

    // emit (identical to the R6-proven epilogue)
    #pragma unroll
    for (int r = 0; r < 8; r++) {
        int pos = t * 8 + r;
        unsigned long long key = A[r];
        int n = (int)(unsigned)key;
        unsigned uh = ~(unsigned)(key >> 32);      // recover score bits
        unsigned orig = (uh & 0x80000000u) ? (uh & 0x7fffffffu) : ~uh;
        float val = __uint_as_float(orig);
        float nm = (pos < ki) ? 1.f : 0.f;
        d_idxg[b * K + pos] = n;
        d_gate[b * K + pos] = tanhf(val) * nm;
        d_nm[b * K + pos]   = nm;
        out[OUT_MASK_OFF + b * K + pos] = nm;
    }
}

// ---------------------------------------------------------------------------
// K5: gather (verbatim R4 — measured 7.9us). grid (K, B), 256 threads.
// ---------------------------------------------------------------------------
__global__ void k_gather(const float* __restrict__ X,
                         const float* __restrict__ adj,
                         float* __restrict__ out) {
    int b = blockIdx.y, i = blockIdx.x, t = threadIdx.x;
    __shared__ int   sidx[K];
    __shared__ float snm[K];
    __shared__ __align__(16) float srow[N];
    sidx[t] = d_idxg[b * K + t];
    snm[t]  = d_nm[b * K + t];
    __syncthreads();

    int ri = sidx[i];
    float nmi = snm[i];
    float gte = d_gate[b * K + i];

    {
        const float4* row4 = (const float4*)(adj + (size_t)b * N * N + (size_t)ri * N);
        ((float4*)srow)[t] = row4[t];
    }
    out[((size_t)b * K + i) * C + t] = X[((size_t)b * N + ri) * C + t] * gte;
    __syncthreads();

    out[OUT_ADJ_OFF + ((size_t)b * K + i) * K + t] = srow[sidx[t]] * nmi * snm[t];
}

// ---------------------------------------------------------------------------
extern "C" void kernel_launch(void* const* d_in, const int* in_sizes, int n_in,
                              void* d_out, int out_size) {
    const float* X    = (const float*)d_in[0];
    const float* adj  = (const float*)d_in[1];
    const float* mask = (const float*)d_in[2];
    const float* Wqkv = (const float*)d_in[3];
    float* out = (float*)d_out;

    k_partial<<<dim3(NCHUNK, B), 256>>>(X);
    k_uvec<<<B, 256>>>(Wqkv);
    k_scores<<<dim3(N / 8, B), 256>>>(X, mask);
    k_sort256<<<dim3(4, B), 32>>>();
    k_merge<<<B, 32>>>(mask, out);
    k_gather<<<dim3(K, B), 256>>>(X, adj, out);
}

// round 8
// speedup vs baseline: 1.0548x; 1.0548x over previous
#include <cuda_runtime.h>
#include <math.h>

#define B 8
#define N 1024
#define C 256
#define K 256
#define C2 512
#define SCALE 0.17677669529663687f   // (C/H)^-0.5 = 1/sqrt(32)

// Output layout: [new_X (8*256*256) | new_adj (8*256*256) | new_mask (8*256)]
#define OUT_ADJ_OFF  (B*K*C)
#define OUT_MASK_OFF (2*B*K*C)

#define NCHUNK 64      // partial-sum chunks per batch (16 rows each)

// ---- scratch ----
__device__ float d_part[B*NCHUNK*C];
__device__ float d_u[B*C];
__device__ float d_scores[B*N];
__device__ int   d_idxg[B*K];
__device__ float d_gate[B*K];
__device__ float d_nm[B*K];

// ---------------------------------------------------------------------------
// K1: partial column sums of X (verbatim R2 — proven rounding).
// ---------------------------------------------------------------------------
__global__ void k_partial(const float* __restrict__ X) {
    int b = blockIdx.y, ch = blockIdx.x, c = threadIdx.x;
    const float* xp = X + ((size_t)b * N + (size_t)ch * 16) * C + c;
    float s = 0.f;
    #pragma unroll
    for (int r = 0; r < 16; r++) s += xp[(size_t)r * C];
    d_part[(b * NCHUNK + ch) * C + c] = s;
}

// ---------------------------------------------------------------------------
// K2: Xsum finish + two matvecs (verbatim R2 — proven rounding).
// ---------------------------------------------------------------------------
__global__ void k_uvec(const float* __restrict__ Wqkv) {
    int b = blockIdx.x, t = threadIdx.x;
    __shared__ float xs[C];
    __shared__ float ks[C];
    float s = 0.f;
    #pragma unroll
    for (int ch = 0; ch < NCHUNK; ch++) s += d_part[(b * NCHUNK + ch) * C + t];
    xs[t] = s;
    __syncthreads();
    float ka = 0.f;
    for (int c = 0; c < C; c++) ka += xs[c] * Wqkv[(size_t)c * C2 + C + t];
    ks[t] = ka;
    __syncthreads();
    const float* wrow = Wqkv + (size_t)t * C2;
    float ua = 0.f;
    for (int j = 0; j < C; j++) ua += wrow[j] * ks[j];
    d_u[b * C + t] = ua;
}

// ---------------------------------------------------------------------------
// K3: scores (verbatim R2 — proven rounding).
// ---------------------------------------------------------------------------
__global__ void k_scores(const float* __restrict__ X,
                         const float* __restrict__ mask) {
    int b = blockIdx.y, t = threadIdx.x;
    __shared__ float us[C];
    us[t] = d_u[b * C + t];
    __syncthreads();
    int warp = t >> 5, lane = t & 31;
    int n = blockIdx.x * 8 + warp;
    const float4* xr = (const float4*)(X + ((size_t)b * N + n) * C);
    const float4* ur = (const float4*)us;
    float acc = 0.f;
    #pragma unroll
    for (int it = 0; it < 2; it++) {
        float4 xv = xr[lane + it * 32];
        float4 uv = ur[lane + it * 32];
        acc += xv.x * uv.x + xv.y * uv.y + xv.z * uv.z + xv.w * uv.w;
    }
    #pragma unroll
    for (int o = 16; o; o >>= 1) acc += __shfl_xor_sync(0xffffffffu, acc, o);
    if (lane == 0) {
        float m = mask[b * N + n];
        d_scores[b * N + n] = (m > 0.f) ? SCALE * acc : -1e9f;
    }
}

// ---------------------------------------------------------------------------
// K4: top-k (verbatim R2 — best measured top-k, 9.1us, proven).
// Hybrid bitonic: j>=32 via shared, j<=16 via warp shuffle.
// Key = (~orderedFloat(score) << 32) | idx ; ascending == desc score,
// ascending index tie-break (matches jax.lax.top_k).
// ---------------------------------------------------------------------------
__global__ void __launch_bounds__(1024, 1)
k_topk(const float* __restrict__ mask, float* __restrict__ out) {
    int b = blockIdx.x, t = threadIdx.x;
    __shared__ unsigned long long sk[N];
    __shared__ float red[32];
    __shared__ int s_ki;

    float f = d_scores[b * N + t];
    unsigned u = __float_as_uint(f);
    u = (u & 0x80000000u) ? ~u : (u | 0x80000000u);
    unsigned long long v = ((unsigned long long)(~u) << 32) | (unsigned)t;

    float ms = mask[b * N + t];
    #pragma unroll
    for (int o = 16; o; o >>= 1) ms += __shfl_xor_sync(0xffffffffu, ms, o);
    if ((t & 31) == 0) red[t >> 5] = ms;
    __syncthreads();
    if (t == 0) {
        float s = 0.f;
        #pragma unroll
        for (int w = 0; w < 32; w++) s += red[w];
        s_ki = (int)ceilf(0.25f * s);
    }

    #pragma unroll
    for (unsigned k = 2; k <= 1024; k <<= 1) {
        bool dir_up = ((t & k) == 0);
        for (unsigned j = k >> 1; j >= 32; j >>= 1) {
            sk[t] = v;
            __syncthreads();
            unsigned long long w = sk[t ^ j];
            bool lower = ((t & j) == 0);
            bool takeMin = (lower == dir_up);
            v = takeMin ? (v < w ? v : w) : (v > w ? v : w);
            __syncthreads();
        }
        unsigned jstart = (k >> 1) < 16u ? (k >> 1) : 16u;
        for (unsigned j = jstart; j >= 1; j >>= 1) {
            unsigned long long w = __shfl_xor_sync(0xffffffffu, v, j);
            bool lower = ((t & j) == 0);
            bool takeMin = (lower == dir_up);
            v = takeMin ? (v < w ? v : w) : (v > w ? v : w);
        }
    }
    sk[t] = v;
    __syncthreads();

    if (t < K) {
        unsigned long long key = sk[t];
        int n = (int)(unsigned)key;
        unsigned uh = ~(unsigned)(key >> 32);
        unsigned orig = (uh & 0x80000000u) ? (uh & 0x7fffffffu) : ~uh;
        float val = __uint_as_float(orig);
        float nm = (t < s_ki) ? 1.f : 0.f;
        d_idxg[b * K + t] = n;
        d_gate[b * K + t] = tanhf(val) * nm;
        d_nm[b * K + t]   = nm;
        out[OUT_MASK_OFF + b * K + t] = nm;
    }
}

// ---------------------------------------------------------------------------
// K5: gather, 2 rows per block. grid (128, 8), 256 threads.
//   new_X[b,i,:]   = X[b, idx[i], :] * gate[i]          (coalesced)
//   new_adj[b,i,j] = adj[b, idx[i], idx[j]] * nm[i]*nm[j]
// 2 adj rows (8KB) staged coalesced concurrently (MLP 2x), idx/nm loads and
// barrier amortized over 2 output rows.
// ---------------------------------------------------------------------------
__global__ void k_gather(const float* __restrict__ X,
                         const float* __restrict__ adj,
                         float* __restrict__ out) {
    int b = blockIdx.y, i0 = blockIdx.x * 2, t = threadIdx.x;
    __shared__ int   sidx[K];
    __shared__ float snm[K];
    __shared__ __align__(16) float srow[2][N];
    sidx[t] = d_idxg[b * K + t];
    snm[t]  = d_nm[b * K + t];
    __syncthreads();

    int ri0 = sidx[i0],     ri1 = sidx[i0 + 1];
    float nmi0 = snm[i0],   nmi1 = snm[i0 + 1];
    float g0 = d_gate[b * K + i0], g1 = d_gate[b * K + i0 + 1];

    // stage both adj rows coalesced (2 independent LDG.128 in flight / thread)
    {
        const float4* r0 = (const float4*)(adj + (size_t)b * N * N + (size_t)ri0 * N);
        const float4* r1 = (const float4*)(adj + (size_t)b * N * N + (size_t)ri1 * N);
        float4 a0 = r0[t];
        float4 a1 = r1[t];
        ((float4*)srow[0])[t] = a0;
        ((float4*)srow[1])[t] = a1;
    }
    // new_X rows (coalesced), overlapped with staging latency
    out[((size_t)b * K + i0)     * C + t] = X[((size_t)b * N + ri0) * C + t] * g0;
    out[((size_t)b * K + i0 + 1) * C + t] = X[((size_t)b * N + ri1) * C + t] * g1;
    __syncthreads();

    int   cj  = sidx[t];
    float nmj = snm[t];
    float a0 = srow[0][cj], a1 = srow[1][cj];
    out[OUT_ADJ_OFF + ((size_t)b * K + i0)     * K + t] = a0 * nmi0 * nmj;
    out[OUT_ADJ_OFF + ((size_t)b * K + i0 + 1) * K + t] = a1 * nmi1 * nmj;
}

// ---------------------------------------------------------------------------
extern "C" void kernel_launch(void* const* d_in, const int* in_sizes, int n_in,
                              void* d_out, int out_size) {
    const float* X    = (const float*)d_in[0];
    const float* adj  = (const float*)d_in[1];
    const float* mask = (const float*)d_in[2];
    const float* Wqkv = (const float*)d_in[3];
    float* out = (float*)d_out;

    k_partial<<<dim3(NCHUNK, B), 256>>>(X);
    k_uvec<<<B, 256>>>(Wqkv);
    k_scores<<<dim3(N / 8, B), 256>>>(X, mask);
    k_topk<<<B, 1024>>>(mask, out);
    k_gather<<<dim3(K / 2, B), 256>>>(X, adj, out);
}